// round 13
// baseline (speedup 1.0000x reference)
#include <cuda_runtime.h>
#include <cuda_fp16.h>
#include <math.h>

// Persistent device scratch (no allocation allowed in kernel_launch).
__device__ __align__(16) __half g_score_h[100032];   // fp16 score table

#define NS_BLOCKS 148
#define NS_THREADS 512

// ---------------------------------------------------------------------------
// Kernel 1: persistent node-score kernel (148 blocks, no wave tail) — R10
// form, measured ~8us. Coalesced SMEM staging; MLP with layer 3 folded in.
// Master node: setup pins it at node 0; serial fallback scan keeps
// correctness for arbitrary inputs (never taken on bench data).
// ---------------------------------------------------------------------------
__global__ void __launch_bounds__(NS_THREADS, 1)
node_score_kernel(const float* __restrict__ x_t,
                  const float* __restrict__ x_t_dt,
                  const float* __restrict__ W1,
                  const float* __restrict__ b1,
                  const float* __restrict__ W2,
                  const float* __restrict__ b2,
                  const float* __restrict__ W3,
                  const float* __restrict__ b3,
                  int n_nodes) {
    __shared__ float sW1[96];
    __shared__ float sb1[32];
    __shared__ __align__(16) float sW2[1024];
    __shared__ float sb2[32];
    __shared__ float sW3[32];
    __shared__ float sb3;
    __shared__ float smx, smy, smz;
    __shared__ __align__(16) float sx[NS_THREADS * 7];
    __shared__ __align__(16) float sxd[NS_THREADS * 7];

    int t = threadIdx.x;

    for (int k = t; k < 96; k += NS_THREADS) sW1[k] = W1[k];
    for (int k = t; k < 1024; k += NS_THREADS) sW2[k] = W2[k];
    if (t < 32) {
        sb1[t] = b1[t];
        sb2[t] = b2[t];
        sW3[t] = W3[t];
    }
    if (t == 0) {
        sb3 = b3[0];
        if (__ldg(&x_t[0]) == 1.0f) {           // fast path: master is node 0
            smx = __ldg(&x_t[1]);
            smy = __ldg(&x_t[2]);
            smz = __ldg(&x_t[3]);
        } else {                                 // fallback (never taken)
            for (int i = 1; i < n_nodes; i++) {
                if (__ldg(&x_t[(size_t)i * 7]) == 1.0f) {
                    smx = __ldg(&x_t[(size_t)i * 7 + 1]);
                    smy = __ldg(&x_t[(size_t)i * 7 + 2]);
                    smz = __ldg(&x_t[(size_t)i * 7 + 3]);
                    break;
                }
            }
        }
    }

    int npb = (n_nodes + NS_BLOCKS - 1) / NS_BLOCKS;
    int node_beg = blockIdx.x * npb;
    int node_end = min(node_beg + npb, n_nodes);

    for (int base = node_beg; base < node_end; base += NS_THREADS) {
        int nrows = min(NS_THREADS, node_end - base);
        int nflt = nrows * 7;
        const float* xr  = x_t    + (size_t)base * 7;
        const float* xdr = x_t_dt + (size_t)base * 7;
        for (int k = t; k < nflt; k += NS_THREADS) {
            sx[k]  = xr[k];
            sxd[k] = xdr[k];
        }
        __syncthreads();

        if (t < nrows) {
            float px = sx[t * 7 + 1];
            float py = sx[t * 7 + 2];
            float pz = sx[t * 7 + 3];
            float dx = sxd[t * 7 + 1] - px;
            float dy = sxd[t * 7 + 2] - py;
            float dz = sxd[t * 7 + 3] - pz;

            float dn = sqrtf(dx * dx + dy * dy + dz * dz);  // velocity_score
            float inv_dn = 1.0f / fmaxf(dn, 1e-12f);        // dt = 1
            float vx = dx * inv_dn, vy = dy * inv_dn, vz = dz * inv_dn;

            float rx = px - smx, ry = py - smy, rz = pz - smz;
            float rn = sqrtf(rx * rx + ry * ry + rz * rz);
            float dist = rn + 1e-6f;
            float na = fmaxf(rn, 1e-6f);
            float nb = fmaxf(sqrtf(vx * vx + vy * vy + vz * vz), 1e-6f);
            float dir_score = (rx * vx + ry * vy + rz * vz) / (na * nb);

            float a0 = 1.0f / dist;
            float a1 = dir_score;
            float a2 = dn;

            float h[32];
#pragma unroll
            for (int j = 0; j < 32; j++) {
                float s = fmaf(a2, sW1[j * 3 + 2],
                         fmaf(a1, sW1[j * 3 + 1],
                         fmaf(a0, sW1[j * 3 + 0], sb1[j])));
                h[j] = fmaxf(s, 0.0f);
            }

            const float4* w2v = reinterpret_cast<const float4*>(sW2);
            float s3 = sb3;
#pragma unroll
            for (int j = 0; j < 32; j++) {
                float s = sb2[j];
#pragma unroll
                for (int k4 = 0; k4 < 8; k4++) {
                    float4 w = w2v[j * 8 + k4];
                    s = fmaf(h[k4 * 4 + 0], w.x, s);
                    s = fmaf(h[k4 * 4 + 1], w.y, s);
                    s = fmaf(h[k4 * 4 + 2], w.z, s);
                    s = fmaf(h[k4 * 4 + 3], w.w, s);
                }
                s3 = fmaf(fmaxf(s, 0.0f), sW3[j], s3);
            }
            float sig = 1.0f / (1.0f + __expf(-s3));
            g_score_h[base + t] = __float2half(sig);
        }
        __syncthreads();
    }
}

// ---------------------------------------------------------------------------
// Kernel 2: gather with TMA bulk-copy prologue overlap.
// One thread issues a cp.async.bulk of the 200KB fp16 table into SMEM
// (mbarrier completion); meanwhile ALL 32 warps gather the first n4/8 edge
// groups directly from L2 (g_score_h is L2-resident). After the mbarrier
// flips, all warps drain the remaining edges from the SMEM table.
// ---------------------------------------------------------------------------
#define G_THREADS 1024
__global__ void __launch_bounds__(G_THREADS, 1)
gather_kernel(const int* __restrict__ tgt,
              float* __restrict__ out,
              int n_edges, int n_nodes) {
    extern __shared__ __align__(16) __half stab[];
    __shared__ __align__(8) unsigned long long mbar;

    int t = threadIdx.x;
    unsigned mbar_addr;
    {
        unsigned long long tmp;
        asm("{ .reg .u64 a; cvta.to.shared.u64 a, %1; cvt.u32.u64 %0, a; }"
            : "=r"(mbar_addr) : "l"(&mbar));
    }
    unsigned stab_addr;
    {
        asm("{ .reg .u64 a; cvta.to.shared.u64 a, %1; cvt.u32.u64 %0, a; }"
            : "=r"(stab_addr) : "l"(stab));
    }

    unsigned copy_bytes = (unsigned)(((n_nodes * 2) + 15) & ~15);

    if (t == 0) {
        asm volatile("mbarrier.init.shared.b64 [%0], %1;"
                     :: "r"(mbar_addr), "r"(1u) : "memory");
    }
    __syncthreads();
    if (t == 0) {
        asm volatile("mbarrier.arrive.expect_tx.shared.b64 _, [%0], %1;"
                     :: "r"(mbar_addr), "r"(copy_bytes) : "memory");
        asm volatile(
            "cp.async.bulk.shared::cluster.global.mbarrier::complete_tx::bytes "
            "[%0], [%1], %2, [%3];"
            :: "r"(stab_addr), "l"((const void*)g_score_h),
               "r"(copy_bytes), "r"(mbar_addr) : "memory");
    }

    int n4 = n_edges >> 2;
    int pre = n4 >> 3;                     // first 1/8: L2-direct during copy
    int stride = gridDim.x * G_THREADS;
    const int4* tv = reinterpret_cast<const int4*>(tgt);
    float4* ov = reinterpret_cast<float4*>(out);

    // Overlap phase: gather straight from L2 while TMA streams the table.
    for (int j = blockIdx.x * G_THREADS + t; j < pre; j += stride) {
        int4 a = tv[j];
        float4 o;
        o.x = __half2float(__ldg(&g_score_h[a.x]));
        o.y = __half2float(__ldg(&g_score_h[a.y]));
        o.z = __half2float(__ldg(&g_score_h[a.z]));
        o.w = __half2float(__ldg(&g_score_h[a.w]));
        ov[j] = o;
    }

    // Wait for the bulk copy (phase parity 0 on a fresh barrier).
    {
        unsigned done;
        asm volatile(
            "{\n\t.reg .pred p;\n\t"
            "mbarrier.try_wait.parity.shared.b64 p, [%1], %2;\n\t"
            "selp.b32 %0, 1, 0, p;\n\t}"
            : "=r"(done) : "r"(mbar_addr), "r"(0u) : "memory");
        while (!done) {
            asm volatile(
                "{\n\t.reg .pred p;\n\t"
                "mbarrier.try_wait.parity.shared.b64 p, [%1], %2;\n\t"
                "selp.b32 %0, 1, 0, p;\n\t}"
                : "=r"(done) : "r"(mbar_addr), "r"(0u) : "memory");
        }
    }
    __syncthreads();

    // Main phase: remaining 7/8 from the SMEM table.
    for (int j = pre + blockIdx.x * G_THREADS + t; j < n4; j += stride) {
        int4 a = tv[j];
        float4 o;
        o.x = __half2float(stab[a.x]);
        o.y = __half2float(stab[a.y]);
        o.z = __half2float(stab[a.z]);
        o.w = __half2float(stab[a.w]);
        ov[j] = o;
    }

    // Tail (n_edges % 4).
    if (blockIdx.x == 0 && t == 0) {
        for (int e = n4 << 2; e < n_edges; e++)
            out[e] = __half2float(stab[tgt[e]]);
    }
}

extern "C" void kernel_launch(void* const* d_in, const int* in_sizes, int n_in,
                              void* d_out, int out_size) {
    const float* x_t    = (const float*)d_in[0];
    const float* x_t_dt = (const float*)d_in[1];
    const int*   edge_index = (const int*)d_in[2];   // int32 (JAX x64 off)
    const float* W1 = (const float*)d_in[3];
    const float* b1 = (const float*)d_in[4];
    const float* W2 = (const float*)d_in[5];
    const float* b2 = (const float*)d_in[6];
    const float* W3 = (const float*)d_in[7];
    const float* b3 = (const float*)d_in[8];
    float* out = (float*)d_out;

    int n_nodes = in_sizes[0] / 7;
    int n_edges = in_sizes[2] / 2;
    const int* tgt = edge_index + n_edges;  // row 1 of (2, E)

    // Kernel 1: persistent node scores.
    node_score_kernel<<<NS_BLOCKS, NS_THREADS>>>(
        x_t, x_t_dt, W1, b1, W2, b2, W3, b3, n_nodes);

    // Kernel 2: gather with TMA-copy overlap.
    size_t smem = ((size_t)((n_nodes * 2 + 15) & ~15)) + 16;
    cudaFuncSetAttribute(gather_kernel,
                         cudaFuncAttributeMaxDynamicSharedMemorySize,
                         (int)smem);
    gather_kernel<<<148, G_THREADS, smem>>>(tgt, out, n_edges, n_nodes);
}

// round 14
// speedup vs baseline: 1.0021x; 1.0021x over previous
#include <cuda_runtime.h>
#include <cuda_fp16.h>
#include <math.h>

// Persistent device scratch (no allocation allowed in kernel_launch).
__device__ __align__(16) __half g_score_h[100032];   // fp16 score table

#define NS_BLOCKS 148
#define NS_THREADS 512

// ---------------------------------------------------------------------------
// Kernel 1: persistent node-score kernel (148 blocks, no wave tail) — R10
// form (best measured). Master node pinned at node 0 by setup; serial
// fallback scan keeps correctness for arbitrary inputs.
// ---------------------------------------------------------------------------
__global__ void __launch_bounds__(NS_THREADS, 1)
node_score_kernel(const float* __restrict__ x_t,
                  const float* __restrict__ x_t_dt,
                  const float* __restrict__ W1,
                  const float* __restrict__ b1,
                  const float* __restrict__ W2,
                  const float* __restrict__ b2,
                  const float* __restrict__ W3,
                  const float* __restrict__ b3,
                  int n_nodes) {
    __shared__ float sW1[96];
    __shared__ float sb1[32];
    __shared__ __align__(16) float sW2[1024];
    __shared__ float sb2[32];
    __shared__ float sW3[32];
    __shared__ float sb3;
    __shared__ float smx, smy, smz;
    __shared__ __align__(16) float sx[NS_THREADS * 7];
    __shared__ __align__(16) float sxd[NS_THREADS * 7];

    int t = threadIdx.x;

    for (int k = t; k < 96; k += NS_THREADS) sW1[k] = W1[k];
    for (int k = t; k < 1024; k += NS_THREADS) sW2[k] = W2[k];
    if (t < 32) {
        sb1[t] = b1[t];
        sb2[t] = b2[t];
        sW3[t] = W3[t];
    }
    if (t == 0) {
        sb3 = b3[0];
        if (__ldg(&x_t[0]) == 1.0f) {           // fast path: master is node 0
            smx = __ldg(&x_t[1]);
            smy = __ldg(&x_t[2]);
            smz = __ldg(&x_t[3]);
        } else {                                 // fallback (never taken)
            for (int i = 1; i < n_nodes; i++) {
                if (__ldg(&x_t[(size_t)i * 7]) == 1.0f) {
                    smx = __ldg(&x_t[(size_t)i * 7 + 1]);
                    smy = __ldg(&x_t[(size_t)i * 7 + 2]);
                    smz = __ldg(&x_t[(size_t)i * 7 + 3]);
                    break;
                }
            }
        }
    }

    int npb = (n_nodes + NS_BLOCKS - 1) / NS_BLOCKS;
    int node_beg = blockIdx.x * npb;
    int node_end = min(node_beg + npb, n_nodes);

    for (int base = node_beg; base < node_end; base += NS_THREADS) {
        int nrows = min(NS_THREADS, node_end - base);
        int nflt = nrows * 7;
        const float* xr  = x_t    + (size_t)base * 7;
        const float* xdr = x_t_dt + (size_t)base * 7;
        for (int k = t; k < nflt; k += NS_THREADS) {
            sx[k]  = xr[k];
            sxd[k] = xdr[k];
        }
        __syncthreads();

        if (t < nrows) {
            float px = sx[t * 7 + 1];
            float py = sx[t * 7 + 2];
            float pz = sx[t * 7 + 3];
            float dx = sxd[t * 7 + 1] - px;
            float dy = sxd[t * 7 + 2] - py;
            float dz = sxd[t * 7 + 3] - pz;

            float dn = sqrtf(dx * dx + dy * dy + dz * dz);  // velocity_score
            float inv_dn = 1.0f / fmaxf(dn, 1e-12f);        // dt = 1
            float vx = dx * inv_dn, vy = dy * inv_dn, vz = dz * inv_dn;

            float rx = px - smx, ry = py - smy, rz = pz - smz;
            float rn = sqrtf(rx * rx + ry * ry + rz * rz);
            float dist = rn + 1e-6f;
            float na = fmaxf(rn, 1e-6f);
            float nb = fmaxf(sqrtf(vx * vx + vy * vy + vz * vz), 1e-6f);
            float dir_score = (rx * vx + ry * vy + rz * vz) / (na * nb);

            float a0 = 1.0f / dist;
            float a1 = dir_score;
            float a2 = dn;

            float h[32];
#pragma unroll
            for (int j = 0; j < 32; j++) {
                float s = fmaf(a2, sW1[j * 3 + 2],
                         fmaf(a1, sW1[j * 3 + 1],
                         fmaf(a0, sW1[j * 3 + 0], sb1[j])));
                h[j] = fmaxf(s, 0.0f);
            }

            const float4* w2v = reinterpret_cast<const float4*>(sW2);
            float s3 = sb3;
#pragma unroll
            for (int j = 0; j < 32; j++) {
                float s = sb2[j];
#pragma unroll
                for (int k4 = 0; k4 < 8; k4++) {
                    float4 w = w2v[j * 8 + k4];
                    s = fmaf(h[k4 * 4 + 0], w.x, s);
                    s = fmaf(h[k4 * 4 + 1], w.y, s);
                    s = fmaf(h[k4 * 4 + 2], w.z, s);
                    s = fmaf(h[k4 * 4 + 3], w.w, s);
                }
                s3 = fmaf(fmaxf(s, 0.0f), sW3[j], s3);
            }
            float sig = 1.0f / (1.0f + __expf(-s3));
            g_score_h[base + t] = __float2half(sig);
        }
        __syncthreads();
    }
}

// ---------------------------------------------------------------------------
// Kernel 2: gather with a TMA double-buffered INDEX pipeline.
// The 200KB fp16 table lives in SMEM (as before), but the edge-index stream
// is also staged into SMEM by cp.async.bulk, two 8KB chunks in flight.
// Inner loop is pure SMEM: LDS.64 (2 indices) -> 2x LDS.U16 -> STG.64.
// The LDG latency chain that pinned previous versions at ~14.5us is gone.
// Chunk = 2048 edges (one per 2 threads... 2 edges per thread).
// ---------------------------------------------------------------------------
#define G_THREADS 1024
#define CHUNK_E   2048                  // edges per chunk
#define CHUNK_B   (CHUNK_E * 4)        // 8192 bytes

__global__ void __launch_bounds__(G_THREADS, 1)
gather_kernel(const int* __restrict__ tgt,
              float* __restrict__ out,
              int n_edges, int n_nodes) {
    extern __shared__ __align__(16) char dsm[];
    __half* stab = reinterpret_cast<__half*>(dsm);
    int tb = ((n_nodes * 2) + 15) & ~15;                 // table bytes (16B mult)
    int* ibuf0 = reinterpret_cast<int*>(dsm + tb);
    int* ibuf1 = reinterpret_cast<int*>(dsm + tb + CHUNK_B);
    __shared__ __align__(8) unsigned long long mbar[2];

    int t = threadIdx.x;

    unsigned mbar_addr[2], ibuf_addr[2];
    {
        unsigned a;
        asm("{ .reg .u64 x; cvta.to.shared.u64 x, %1; cvt.u32.u64 %0, x; }"
            : "=r"(a) : "l"(&mbar[0]));
        mbar_addr[0] = a; mbar_addr[1] = a + 8;
        asm("{ .reg .u64 x; cvta.to.shared.u64 x, %1; cvt.u32.u64 %0, x; }"
            : "=r"(a) : "l"(ibuf0));
        ibuf_addr[0] = a; ibuf_addr[1] = a + CHUNK_B;
    }

    int nchunks = (n_edges + CHUNK_E - 1) / CHUNK_E;

    if (t == 0) {
        asm volatile("mbarrier.init.shared.b64 [%0], %1;"
                     :: "r"(mbar_addr[0]), "r"(1u) : "memory");
        asm volatile("mbarrier.init.shared.b64 [%0], %1;"
                     :: "r"(mbar_addr[1]), "r"(1u) : "memory");
    }
    __syncthreads();

    // A chunk is TMA-eligible iff it is full (guards the last partial chunk
    // against overreading the input buffer).
    // Prologue: issue the first two chunks for this block.
    if (t == 0) {
#pragma unroll
        for (int i = 0; i < 2; i++) {
            int ci = blockIdx.x + i * gridDim.x;
            if (ci < nchunks && (ci * CHUNK_E + CHUNK_E) <= n_edges) {
                asm volatile("mbarrier.arrive.expect_tx.shared.b64 _, [%0], %1;"
                             :: "r"(mbar_addr[i]), "r"((unsigned)CHUNK_B) : "memory");
                asm volatile(
                    "cp.async.bulk.shared::cluster.global.mbarrier::complete_tx::bytes "
                    "[%0], [%1], %2, [%3];"
                    :: "r"(ibuf_addr[i]), "l"((const void*)(tgt + ci * CHUNK_E)),
                       "r"((unsigned)CHUNK_B), "r"(mbar_addr[i]) : "memory");
            }
        }
    }

    // Table copy (TMA index fetches stream in the background).
    {
        int n8 = (n_nodes + 7) >> 3;
        const uint4* src = reinterpret_cast<const uint4*>(g_score_h);
        uint4* dst = reinterpret_cast<uint4*>(stab);
        for (int k = t; k < n8; k += G_THREADS) dst[k] = src[k];
    }
    __syncthreads();

    // Main pipeline.
    int ph[2] = {0, 0};
    for (int i = 0; ; i++) {
        int ci = blockIdx.x + i * gridDim.x;
        if (ci >= nchunks) break;
        int s = i & 1;
        int ebase = ci * CHUNK_E;
        bool full = (ebase + CHUNK_E) <= n_edges;

        if (full) {
            // Wait for this stage's TMA.
            unsigned done;
            do {
                asm volatile(
                    "{\n\t.reg .pred p;\n\t"
                    "mbarrier.try_wait.parity.shared.b64 p, [%1], %2;\n\t"
                    "selp.b32 %0, 1, 0, p;\n\t}"
                    : "=r"(done) : "r"(mbar_addr[s]), "r"((unsigned)ph[s]) : "memory");
            } while (!done);
            ph[s] ^= 1;

            // Pure-SMEM inner step: LDS.64 -> 2x LDS.U16 -> STG.64.
            const int* ib = (s == 0) ? ibuf0 : ibuf1;
            int2 a = reinterpret_cast<const int2*>(ib)[t];
            float2 o;
            o.x = __half2float(stab[a.x]);
            o.y = __half2float(stab[a.y]);
            reinterpret_cast<float2*>(out + ebase)[t] = o;

            __syncthreads();   // all reads of ibuf[s] done before re-issue

            // Issue TMA for the chunk 2 steps ahead into this stage.
            if (t == 0) {
                int cn = ci + 2 * gridDim.x;
                if (cn < nchunks && (cn * CHUNK_E + CHUNK_E) <= n_edges) {
                    asm volatile("mbarrier.arrive.expect_tx.shared.b64 _, [%0], %1;"
                                 :: "r"(mbar_addr[s]), "r"((unsigned)CHUNK_B) : "memory");
                    asm volatile(
                        "cp.async.bulk.shared::cluster.global.mbarrier::complete_tx::bytes "
                        "[%0], [%1], %2, [%3];"
                        :: "r"(ibuf_addr[s]), "l"((const void*)(tgt + cn * CHUNK_E)),
                           "r"((unsigned)CHUNK_B), "r"(mbar_addr[s]) : "memory");
                }
            }
        } else {
            // Last partial chunk: direct gmem path (no TMA was issued).
            int e0 = ebase + 2 * t;
            if (e0 < n_edges)     out[e0]     = __half2float(stab[__ldg(&tgt[e0])]);
            if (e0 + 1 < n_edges) out[e0 + 1] = __half2float(stab[__ldg(&tgt[e0 + 1])]);
        }
    }
}

extern "C" void kernel_launch(void* const* d_in, const int* in_sizes, int n_in,
                              void* d_out, int out_size) {
    const float* x_t    = (const float*)d_in[0];
    const float* x_t_dt = (const float*)d_in[1];
    const int*   edge_index = (const int*)d_in[2];   // int32 (JAX x64 off)
    const float* W1 = (const float*)d_in[3];
    const float* b1 = (const float*)d_in[4];
    const float* W2 = (const float*)d_in[5];
    const float* b2 = (const float*)d_in[6];
    const float* W3 = (const float*)d_in[7];
    const float* b3 = (const float*)d_in[8];
    float* out = (float*)d_out;

    int n_nodes = in_sizes[0] / 7;
    int n_edges = in_sizes[2] / 2;
    const int* tgt = edge_index + n_edges;  // row 1 of (2, E)

    // Kernel 1: persistent node scores.
    node_score_kernel<<<NS_BLOCKS, NS_THREADS>>>(
        x_t, x_t_dt, W1, b1, W2, b2, W3, b3, n_nodes);

    // Kernel 2: gather with TMA index pipeline.
    size_t tb = ((size_t)(n_nodes * 2) + 15) & ~15ull;   // 200000B
    size_t smem = tb + 2 * CHUNK_B + 32;                  // ~216.4KB
    cudaFuncSetAttribute(gather_kernel,
                         cudaFuncAttributeMaxDynamicSharedMemorySize,
                         (int)smem);
    gather_kernel<<<148, G_THREADS, smem>>>(tgt, out, n_edges, n_nodes);
}

// round 15
// speedup vs baseline: 1.2577x; 1.2552x over previous
#include <cuda_runtime.h>
#include <cuda_fp16.h>
#include <math.h>

// Persistent device scratch (no allocation allowed in kernel_launch).
__device__ __align__(16) __half g_score_h[100032];   // fp16 score table

#define NS_BLOCKS 148
#define NS_THREADS 512

// ---------------------------------------------------------------------------
// Kernel 1: persistent node-score kernel (148 blocks, no wave tail) — R10
// form (best measured, ~8us). Coalesced SMEM staging of stride-7 rows; MLP
// 3->32->32->1 with layer 3 folded into the layer-2 loop; sigmoid -> fp16.
// Master node: setup pins it at node 0; serial fallback scan keeps
// correctness for arbitrary inputs (never taken on bench data).
// ---------------------------------------------------------------------------
__global__ void __launch_bounds__(NS_THREADS, 1)
node_score_kernel(const float* __restrict__ x_t,
                  const float* __restrict__ x_t_dt,
                  const float* __restrict__ W1,
                  const float* __restrict__ b1,
                  const float* __restrict__ W2,
                  const float* __restrict__ b2,
                  const float* __restrict__ W3,
                  const float* __restrict__ b3,
                  int n_nodes) {
    __shared__ float sW1[96];
    __shared__ float sb1[32];
    __shared__ __align__(16) float sW2[1024];
    __shared__ float sb2[32];
    __shared__ float sW3[32];
    __shared__ float sb3;
    __shared__ float smx, smy, smz;
    __shared__ __align__(16) float sx[NS_THREADS * 7];
    __shared__ __align__(16) float sxd[NS_THREADS * 7];

    int t = threadIdx.x;

    for (int k = t; k < 96; k += NS_THREADS) sW1[k] = W1[k];
    for (int k = t; k < 1024; k += NS_THREADS) sW2[k] = W2[k];
    if (t < 32) {
        sb1[t] = b1[t];
        sb2[t] = b2[t];
        sW3[t] = W3[t];
    }
    if (t == 0) {
        sb3 = b3[0];
        if (__ldg(&x_t[0]) == 1.0f) {           // fast path: master is node 0
            smx = __ldg(&x_t[1]);
            smy = __ldg(&x_t[2]);
            smz = __ldg(&x_t[3]);
        } else {                                 // fallback (never taken)
            for (int i = 1; i < n_nodes; i++) {
                if (__ldg(&x_t[(size_t)i * 7]) == 1.0f) {
                    smx = __ldg(&x_t[(size_t)i * 7 + 1]);
                    smy = __ldg(&x_t[(size_t)i * 7 + 2]);
                    smz = __ldg(&x_t[(size_t)i * 7 + 3]);
                    break;
                }
            }
        }
    }

    int npb = (n_nodes + NS_BLOCKS - 1) / NS_BLOCKS;
    int node_beg = blockIdx.x * npb;
    int node_end = min(node_beg + npb, n_nodes);

    for (int base = node_beg; base < node_end; base += NS_THREADS) {
        int nrows = min(NS_THREADS, node_end - base);
        int nflt = nrows * 7;
        const float* xr  = x_t    + (size_t)base * 7;
        const float* xdr = x_t_dt + (size_t)base * 7;
        for (int k = t; k < nflt; k += NS_THREADS) {
            sx[k]  = xr[k];
            sxd[k] = xdr[k];
        }
        __syncthreads();

        if (t < nrows) {
            float px = sx[t * 7 + 1];
            float py = sx[t * 7 + 2];
            float pz = sx[t * 7 + 3];
            float dx = sxd[t * 7 + 1] - px;
            float dy = sxd[t * 7 + 2] - py;
            float dz = sxd[t * 7 + 3] - pz;

            float dn = sqrtf(dx * dx + dy * dy + dz * dz);  // velocity_score
            float inv_dn = 1.0f / fmaxf(dn, 1e-12f);        // dt = 1
            float vx = dx * inv_dn, vy = dy * inv_dn, vz = dz * inv_dn;

            float rx = px - smx, ry = py - smy, rz = pz - smz;
            float rn = sqrtf(rx * rx + ry * ry + rz * rz);
            float dist = rn + 1e-6f;
            float na = fmaxf(rn, 1e-6f);
            float nb = fmaxf(sqrtf(vx * vx + vy * vy + vz * vz), 1e-6f);
            float dir_score = (rx * vx + ry * vy + rz * vz) / (na * nb);

            float a0 = 1.0f / dist;
            float a1 = dir_score;
            float a2 = dn;

            float h[32];
#pragma unroll
            for (int j = 0; j < 32; j++) {
                float s = fmaf(a2, sW1[j * 3 + 2],
                         fmaf(a1, sW1[j * 3 + 1],
                         fmaf(a0, sW1[j * 3 + 0], sb1[j])));
                h[j] = fmaxf(s, 0.0f);
            }

            const float4* w2v = reinterpret_cast<const float4*>(sW2);
            float s3 = sb3;
#pragma unroll
            for (int j = 0; j < 32; j++) {
                float s = sb2[j];
#pragma unroll
                for (int k4 = 0; k4 < 8; k4++) {
                    float4 w = w2v[j * 8 + k4];
                    s = fmaf(h[k4 * 4 + 0], w.x, s);
                    s = fmaf(h[k4 * 4 + 1], w.y, s);
                    s = fmaf(h[k4 * 4 + 2], w.z, s);
                    s = fmaf(h[k4 * 4 + 3], w.w, s);
                }
                s3 = fmaf(fmaxf(s, 0.0f), sW3[j], s3);
            }
            float sig = 1.0f / (1.0f + __expf(-s3));
            g_score_h[base + t] = __float2half(sig);
        }
        __syncthreads();
    }
}

// ---------------------------------------------------------------------------
// Kernel 2: persistent gather (simplest proven form + two micro-opts).
//  - First index group prefetched into registers BEFORE the table-copy
//    barrier: its global-load latency hides under the 200KB copy.
//  - Output stores use st.global.cs (streaming, evict-first): the 25.6MB
//    output is never re-read, so don't let it displace the L2-hot indices.
// ---------------------------------------------------------------------------
#define G_THREADS 1024
__global__ void __launch_bounds__(G_THREADS, 1)
gather_kernel(const int* __restrict__ tgt,
              float* __restrict__ out,
              int n_edges, int n_nodes) {
    extern __shared__ __align__(16) __half stab[];

    int t = threadIdx.x;
    int n4 = n_edges >> 2;
    int stride = gridDim.x * G_THREADS;
    const int4* tv = reinterpret_cast<const int4*>(tgt);
    float4* ov = reinterpret_cast<float4*>(out);

    // Prefetch this thread's first index group (latency hides under copy).
    int j0 = blockIdx.x * G_THREADS + t;
    int4 a0;
    bool have0 = (j0 < n4);
    if (have0) a0 = __ldg(&tv[j0]);

    // Cooperative table load (uint4 = 8 halves, coalesced).
    int n8 = (n_nodes + 7) >> 3;
    const uint4* src = reinterpret_cast<const uint4*>(g_score_h);
    uint4* dst = reinterpret_cast<uint4*>(stab);
    for (int k = t; k < n8; k += G_THREADS) dst[k] = src[k];
    __syncthreads();

    // First group (indices already in registers).
    if (have0) {
        float4 o;
        o.x = __half2float(stab[a0.x]);
        o.y = __half2float(stab[a0.y]);
        o.z = __half2float(stab[a0.z]);
        o.w = __half2float(stab[a0.w]);
        __stcs(&ov[j0], o);
    }

    // Remaining groups.
    for (int j = j0 + stride; j < n4; j += stride) {
        int4 a = __ldg(&tv[j]);
        float4 o;
        o.x = __half2float(stab[a.x]);
        o.y = __half2float(stab[a.y]);
        o.z = __half2float(stab[a.z]);
        o.w = __half2float(stab[a.w]);
        __stcs(&ov[j], o);
    }

    // Tail (n_edges % 4; empty for 6.4M edges).
    if (blockIdx.x == 0 && t == 0) {
        for (int e = n4 << 2; e < n_edges; e++)
            out[e] = __half2float(stab[__ldg(&tgt[e])]);
    }
}

extern "C" void kernel_launch(void* const* d_in, const int* in_sizes, int n_in,
                              void* d_out, int out_size) {
    const float* x_t    = (const float*)d_in[0];
    const float* x_t_dt = (const float*)d_in[1];
    const int*   edge_index = (const int*)d_in[2];   // int32 (JAX x64 off)
    const float* W1 = (const float*)d_in[3];
    const float* b1 = (const float*)d_in[4];
    const float* W2 = (const float*)d_in[5];
    const float* b2 = (const float*)d_in[6];
    const float* W3 = (const float*)d_in[7];
    const float* b3 = (const float*)d_in[8];
    float* out = (float*)d_out;

    int n_nodes = in_sizes[0] / 7;
    int n_edges = in_sizes[2] / 2;
    const int* tgt = edge_index + n_edges;  // row 1 of (2, E)

    // Kernel 1: persistent node scores.
    node_score_kernel<<<NS_BLOCKS, NS_THREADS>>>(
        x_t, x_t_dt, W1, b1, W2, b2, W3, b3, n_nodes);

    // Kernel 2: persistent gather with SMEM-resident fp16 table.
    size_t smem = ((size_t)(n_nodes + 7) & ~7ull) * sizeof(__half) + 16;
    cudaFuncSetAttribute(gather_kernel,
                         cudaFuncAttributeMaxDynamicSharedMemorySize,
                         (int)smem);
    gather_kernel<<<148, G_THREADS, smem>>>(tgt, out, n_edges, n_nodes);
}